// round 8
// baseline (speedup 1.0000x reference)
#include <cuda_runtime.h>
#include <cstdint>

#define NT   2048
#define DIN  1024
#define DHID 4096
#define DOUT 1024
#define NE   8

// ---------------- device scratch ----------------
__device__ int   g_count[NE];
__device__ int   g_hrow[NE][NT];     // hrow = token*2 + k
__device__ float g_cw[NE][NT];       // combine weight
__device__ float g_h[NT * 2][DHID];  // hidden acts (tf32-rounded at write)
__device__ float g_xr[NT][DIN];      // x (tf32-rounded)

// ---------------- helpers ----------------
__device__ __forceinline__ float rna_f(float f) {
    uint32_t u;
    asm volatile("cvt.rna.tf32.f32 %0, %1;" : "=r"(u) : "f"(f));
    return __uint_as_float(u);
}
__device__ __forceinline__ uint32_t f2tf32(float f) {
    uint32_t u;
    asm volatile("cvt.rna.tf32.f32 %0, %1;" : "=r"(u) : "f"(f));
    return u;
}
__device__ __forceinline__ void mma_tf32(float* c, const uint32_t* a, const uint32_t* b) {
    asm volatile(
        "mma.sync.aligned.m16n8k8.row.col.f32.tf32.tf32.f32 "
        "{%0,%1,%2,%3}, {%4,%5,%6,%7}, {%8,%9}, {%0,%1,%2,%3};"
        : "+f"(c[0]), "+f"(c[1]), "+f"(c[2]), "+f"(c[3])
        : "r"(a[0]), "r"(a[1]), "r"(a[2]), "r"(a[3]), "r"(b[0]), "r"(b[1]));
}
#define CP_ASYNC16(dst, src) \
    asm volatile("cp.async.cg.shared.global [%0], [%1], 16;\n" :: "r"(dst), "l"(src))
#define CP_COMMIT() asm volatile("cp.async.commit_group;\n" ::)
#define CP_WAIT(n)  asm volatile("cp.async.wait_group %0;\n" :: "n"(n))

// smem layout
#define A_STRIDE 36     // 32 + 4 pad (floats)
#define B_STRIDE 136    // 128 + 8 pad (floats)
#define A_BUF (128 * A_STRIDE)
#define B_BUF (32 * B_STRIDE)
#define STAGE_FLOATS (A_BUF + B_BUF)             // 8960
#define NSTAGE 3
#define SMEM_BYTES (NSTAGE * STAGE_FLOATS * 4)   // 107520

// ---------------- prepass: round x (8 MB, ~4us) ----------------
__global__ void round_x_kernel(const float* __restrict__ src, float* __restrict__ dst) {
    int i = blockIdx.x * blockDim.x + threadIdx.x;
    float4 v = ((const float4*)src)[i];
    v.x = rna_f(v.x); v.y = rna_f(v.y); v.z = rna_f(v.z); v.w = rna_f(v.w);
    ((float4*)dst)[i] = v;
}

// ---------------- init ----------------
__global__ void init_kernel(float* __restrict__ out) {
    int i = blockIdx.x * blockDim.x + threadIdx.x;
    if (i < NE) g_count[i] = 0;
    int n4 = NT * DOUT / 4;
    if (i < n4) ((float4*)out)[i] = make_float4(0.f, 0.f, 0.f, 0.f);
}

// ---------------- router: 1 warp per token ----------------
__global__ void __launch_bounds__(256) router_kernel(
    const float* __restrict__ x, const float* __restrict__ Wr,
    const float* __restrict__ br)
{
    int warp = threadIdx.x >> 5;
    int lane = threadIdx.x & 31;
    int t = blockIdx.x * 8 + warp;
    if (t >= NT) return;

    const float* xr = x + (size_t)t * DIN;
    float acc[NE];
#pragma unroll
    for (int e = 0; e < NE; e++) acc[e] = 0.f;
    for (int d = lane; d < DIN; d += 32) {
        float xv = xr[d];
        const float* w = Wr + (size_t)d * NE;
#pragma unroll
        for (int e = 0; e < NE; e++) acc[e] += xv * w[e];
    }
#pragma unroll
    for (int e = 0; e < NE; e++) {
#pragma unroll
        for (int off = 16; off; off >>= 1)
            acc[e] += __shfl_xor_sync(0xffffffffu, acc[e], off);
    }
    if (lane == 0) {
        float logit[NE], p[NE];
        float mx = -1e30f;
#pragma unroll
        for (int e = 0; e < NE; e++) { logit[e] = acc[e] + br[e]; mx = fmaxf(mx, logit[e]); }
        float s = 0.f;
#pragma unroll
        for (int e = 0; e < NE; e++) { p[e] = expf(logit[e] - mx); s += p[e]; }
        float inv = 1.f / s;
#pragma unroll
        for (int e = 0; e < NE; e++) p[e] *= inv;
        int i0 = 0;
#pragma unroll
        for (int e = 1; e < NE; e++) if (p[e] > p[i0]) i0 = e;
        int i1 = (i0 == 0) ? 1 : 0;
#pragma unroll
        for (int e = 0; e < NE; e++) { if (e == i0) continue; if (p[e] > p[i1]) i1 = e; }
        int idx[2] = { i0, i1 };
#pragma unroll
        for (int k = 0; k < 2; k++) {
            int e = idx[k];
            int pos = atomicAdd(&g_count[e], 1);
            g_hrow[e][pos] = t * 2 + k;
            g_cw[e][pos]   = p[e];
        }
    }
}

// ============================================================================
// tf32 MMA tile core (R6 compute). BM=128, BN=128, BK=32, 256 thr, 8 warps
// (2x4), warp tile 64x32. A pre-rounded (raw bits); B cvt at fragment load.
// 3-stage cp.async pipeline, ONE __syncthreads per K-tile.
// ============================================================================

template<int N_DIM>
__device__ __forceinline__ void load_tile(
    float* As, float* Bs, const float* __restrict__ Asrc_base,
    const int* s_row, const float* __restrict__ Bsrc,
    int k0, int tid, int a_src_ld)
{
    // A: 128 rows x 32 floats = 1024 float4; 4 per thread (gathered rows)
#pragma unroll
    for (int i = 0; i < 4; i++) {
        int c   = tid + i * 256;
        int row = c >> 3;
        int c4  = (c & 7) * 4;
        const float* src = Asrc_base + (size_t)s_row[row] * a_src_ld + k0 + c4;
        uint32_t dst = (uint32_t)__cvta_generic_to_shared(As + row * A_STRIDE + c4);
        CP_ASYNC16(dst, src);
    }
    // B: 32 rows x 128 floats = 1024 float4; 4 per thread
#pragma unroll
    for (int i = 0; i < 4; i++) {
        int c   = tid + i * 256;
        int row = c >> 5;
        int c4  = (c & 31) * 4;
        const float* src = Bsrc + (size_t)row * N_DIM + c4;
        uint32_t dst = (uint32_t)__cvta_generic_to_shared(Bs + row * B_STRIDE + c4);
        CP_ASYNC16(dst, src);
    }
    CP_COMMIT();
}

__device__ __forceinline__ void compute_tile(
    const float* Asf, const float* Bs, float acc[4][4][4], int lane, int wm, int wn)
{
    const uint32_t* As = (const uint32_t*)Asf;   // pre-rounded: raw bits
    int g  = lane >> 2;
    int t4 = lane & 3;
#pragma unroll
    for (int kk = 0; kk < 4; kk++) {
        int k = kk * 8;
        uint32_t af[4][4];
        uint32_t bf[4][2];
#pragma unroll
        for (int mi = 0; mi < 4; mi++) {
            int r0 = wm * 64 + mi * 16 + g;
            af[mi][0] = As[(r0    ) * A_STRIDE + k + t4    ];
            af[mi][1] = As[(r0 + 8) * A_STRIDE + k + t4    ];
            af[mi][2] = As[(r0    ) * A_STRIDE + k + t4 + 4];
            af[mi][3] = As[(r0 + 8) * A_STRIDE + k + t4 + 4];
        }
#pragma unroll
        for (int ni = 0; ni < 4; ni++) {
            int col = wn * 32 + ni * 8 + g;
            bf[ni][0] = f2tf32(Bs[(k + t4    ) * B_STRIDE + col]);
            bf[ni][1] = f2tf32(Bs[(k + t4 + 4) * B_STRIDE + col]);
        }
#pragma unroll
        for (int mi = 0; mi < 4; mi++)
#pragma unroll
            for (int ni = 0; ni < 4; ni++)
                mma_tf32(acc[mi][ni], af[mi], bf[ni]);
    }
}

// ---------------- shared mainloop: 3 stages, 1 sync/tile ----------------
template<int N_DIM>
__device__ __forceinline__ void gemm_mainloop(
    float* smem, const float* Abase, int lda, const int* s_row,
    const float* Bsrc, int KT, int tid,
    float acc[4][4][4], int lane, int wm, int wn)
{
    float* stg[NSTAGE];
#pragma unroll
    for (int s = 0; s < NSTAGE; s++) stg[s] = smem + s * STAGE_FLOATS;

    load_tile<N_DIM>(stg[0], stg[0] + A_BUF, Abase, s_row, Bsrc, 0, tid, lda);
    load_tile<N_DIM>(stg[1], stg[1] + A_BUF, Abase, s_row,
                     Bsrc + (size_t)32 * N_DIM, 32, tid, lda);

    for (int kt = 0; kt < KT; kt++) {
        if (kt + 1 < KT) { CP_WAIT(1); } else { CP_WAIT(0); }  // stage kt arrived
        __syncthreads();   // publishes stage kt AND retires compute(kt-1)
        int jn = kt + 2;
        if (jn < KT)       // safe: buffer jn%3 last touched by compute(kt-1)
            load_tile<N_DIM>(stg[jn % NSTAGE], stg[jn % NSTAGE] + A_BUF, Abase,
                             s_row, Bsrc + (size_t)jn * 32 * N_DIM, jn * 32, tid, lda);
        int s = kt % NSTAGE;
        compute_tile(stg[s], stg[s] + A_BUF, acc, lane, wm, wn);
    }
}

// ---------------- GEMM1: h = rna(relu(xr @ W1 + b1)) ----------------
__global__ void __launch_bounds__(256) gemm1_kernel(
    const float* __restrict__ W1, const float* __restrict__ b1)
{
    extern __shared__ float smem[];
    int e = blockIdx.z;
    int count = g_count[e];
    int r0 = blockIdx.y * 128;
    if (r0 >= count) return;
    int n0 = blockIdx.x * 128;

    __shared__ int s_hrow[128];
    __shared__ int s_tok[128];

    int tid = threadIdx.x;
    if (tid < 128) {
        int r = r0 + tid;
        if (r < count) { int hr = g_hrow[e][r]; s_hrow[tid] = hr; s_tok[tid] = hr >> 1; }
        else           { s_hrow[tid] = -1;      s_tok[tid] = g_hrow[e][0] >> 1; }
    }
    __syncthreads();

    int lane = tid & 31, warp = tid >> 5;
    int wm = warp >> 2, wn = warp & 3;

    float acc[4][4][4];
#pragma unroll
    for (int a = 0; a < 4; a++)
#pragma unroll
        for (int b = 0; b < 4; b++)
#pragma unroll
            for (int c = 0; c < 4; c++) acc[a][b][c] = 0.f;

    const float* W1e = W1 + (size_t)e * DIN * DHID + n0;
    gemm_mainloop<DHID>(smem, &g_xr[0][0], DIN, s_tok, W1e, DIN / 32, tid,
                        acc, lane, wm, wn);

    const float* b1e = b1 + (size_t)e * DHID + n0;
    int g = lane >> 2, t4 = lane & 3;
#pragma unroll
    for (int mi = 0; mi < 4; mi++) {
#pragma unroll
        for (int half = 0; half < 2; half++) {
            int m  = wm * 64 + mi * 16 + g + half * 8;
            int hr = s_hrow[m];
            if (hr < 0) continue;
#pragma unroll
            for (int ni = 0; ni < 4; ni++) {
                int col = wn * 32 + ni * 8 + t4 * 2;
                float c0 = acc[mi][ni][half * 2 + 0] + b1e[col];
                float c1 = acc[mi][ni][half * 2 + 1] + b1e[col + 1];
                float2 v = make_float2(rna_f(fmaxf(c0, 0.f)), rna_f(fmaxf(c1, 0.f)));
                *(float2*)(&g_h[hr][n0 + col]) = v;
            }
        }
    }
}

// ---------------- GEMM2: out[tok] += cw * (h @ W2 + b2) ----------------
__global__ void __launch_bounds__(256) gemm2_kernel(
    const float* __restrict__ W2, const float* __restrict__ b2,
    float* __restrict__ out)
{
    extern __shared__ float smem[];
    int e = blockIdx.z;
    int count = g_count[e];
    int r0 = blockIdx.y * 128;
    if (r0 >= count) return;
    int n0 = blockIdx.x * 128;

    __shared__ int   s_hrow[128];
    __shared__ float s_cw[128];

    int tid = threadIdx.x;
    if (tid < 128) {
        int r = r0 + tid;
        if (r < count) { s_hrow[tid] = g_hrow[e][r]; s_cw[tid] = g_cw[e][r]; }
        else           { s_hrow[tid] = g_hrow[e][0]; s_cw[tid] = -1.f; }
    }
    __syncthreads();

    int lane = tid & 31, warp = tid >> 5;
    int wm = warp >> 2, wn = warp & 3;

    float acc[4][4][4];
#pragma unroll
    for (int a = 0; a < 4; a++)
#pragma unroll
        for (int b = 0; b < 4; b++)
#pragma unroll
            for (int c = 0; c < 4; c++) acc[a][b][c] = 0.f;

    const float* W2e = W2 + (size_t)e * DHID * DOUT + n0;
    gemm_mainloop<DOUT>(smem, &g_h[0][0], DHID, s_hrow, W2e, DHID / 32, tid,
                        acc, lane, wm, wn);

    const float* b2e = b2 + (size_t)e * DOUT + n0;
    int g = lane >> 2, t4 = lane & 3;
#pragma unroll
    for (int mi = 0; mi < 4; mi++) {
#pragma unroll
        for (int half = 0; half < 2; half++) {
            int m  = wm * 64 + mi * 16 + g + half * 8;
            float w = s_cw[m];
            if (w < 0.f) continue;
            int tok = s_hrow[m] >> 1;
#pragma unroll
            for (int ni = 0; ni < 4; ni++) {
                int col = wn * 32 + ni * 8 + t4 * 2;
                float c0 = w * (acc[mi][ni][half * 2 + 0] + b2e[col]);
                float c1 = w * (acc[mi][ni][half * 2 + 1] + b2e[col + 1]);
                float* o = out + (size_t)tok * DOUT + n0 + col;
                atomicAdd(o + 0, c0);
                atomicAdd(o + 1, c1);
            }
        }
    }
}

// ---------------- launch ----------------
extern "C" void kernel_launch(void* const* d_in, const int* in_sizes, int n_in,
                              void* d_out, int out_size) {
    const float* x  = (const float*)d_in[0];
    const float* Wr = (const float*)d_in[1];
    const float* br = (const float*)d_in[2];
    const float* W1 = (const float*)d_in[3];
    const float* b1 = (const float*)d_in[4];
    const float* W2 = (const float*)d_in[5];
    const float* b2 = (const float*)d_in[6];
    float* out = (float*)d_out;

    cudaFuncSetAttribute(gemm1_kernel, cudaFuncAttributeMaxDynamicSharedMemorySize, SMEM_BYTES);
    cudaFuncSetAttribute(gemm2_kernel, cudaFuncAttributeMaxDynamicSharedMemorySize, SMEM_BYTES);

    float* xr;  cudaGetSymbolAddress((void**)&xr, g_xr);

    round_x_kernel<<<NT * DIN / 1024, 256>>>(x, xr);
    init_kernel<<<2048, 256>>>(out);
    router_kernel<<<NT / 8, 256>>>(x, Wr, br);
    gemm1_kernel<<<dim3(DHID / 128, NT / 128, NE), 256, SMEM_BYTES>>>(W1, b1);
    gemm2_kernel<<<dim3(DOUT / 128, NT / 128, NE), 256, SMEM_BYTES>>>(W2, b2, out);
}

// round 9
// speedup vs baseline: 1.3728x; 1.3728x over previous
#include <cuda_runtime.h>
#include <cstdint>

#define NT   2048
#define DIN  1024
#define DHID 4096
#define DOUT 1024
#define NE   8

// ---------------- device scratch ----------------
__device__ int   g_count[NE];
__device__ int   g_hrow[NE][NT];     // hrow = token*2 + k
__device__ float g_cw[NE][NT];       // combine weight
__device__ float g_h[NT * 2][DHID];  // hidden acts (tf32-rounded at write)
__device__ float g_xr[NT][DIN];      // x (tf32-rounded)

// ---------------- helpers ----------------
__device__ __forceinline__ float rna_f(float f) {
    uint32_t u;
    asm volatile("cvt.rna.tf32.f32 %0, %1;" : "=r"(u) : "f"(f));
    return __uint_as_float(u);
}
__device__ __forceinline__ uint32_t f2tf32(float f) {
    uint32_t u;
    asm volatile("cvt.rna.tf32.f32 %0, %1;" : "=r"(u) : "f"(f));
    return u;
}
__device__ __forceinline__ void mma_tf32(float* c, const uint32_t* a, const uint32_t* b) {
    asm volatile(
        "mma.sync.aligned.m16n8k8.row.col.f32.tf32.tf32.f32 "
        "{%0,%1,%2,%3}, {%4,%5,%6,%7}, {%8,%9}, {%0,%1,%2,%3};"
        : "+f"(c[0]), "+f"(c[1]), "+f"(c[2]), "+f"(c[3])
        : "r"(a[0]), "r"(a[1]), "r"(a[2]), "r"(a[3]), "r"(b[0]), "r"(b[1]));
}
#define CP_ASYNC16(dst, src) \
    asm volatile("cp.async.cg.shared.global [%0], [%1], 16;\n" :: "r"(dst), "l"(src))
#define CP_COMMIT() asm volatile("cp.async.commit_group;\n" ::)
#define CP_WAIT(n)  asm volatile("cp.async.wait_group %0;\n" :: "n"(n))

// smem layout (identical to R2/R6)
#define A_STRIDE 36     // 32 + 4 pad (floats)
#define B_STRIDE 136    // 128 + 8 pad (floats)
#define A_BUF (128 * A_STRIDE)
#define B_BUF (32 * B_STRIDE)
#define SMEM_FLOATS (2 * A_BUF + 2 * B_BUF)   // 17664 floats = 70656 B

// ---------------- prepass: round x (8 MB, ~4us) ----------------
__global__ void round_x_kernel(const float* __restrict__ src, float* __restrict__ dst) {
    int i = blockIdx.x * blockDim.x + threadIdx.x;
    float4 v = ((const float4*)src)[i];
    v.x = rna_f(v.x); v.y = rna_f(v.y); v.z = rna_f(v.z); v.w = rna_f(v.w);
    ((float4*)dst)[i] = v;
}

// ---------------- init ----------------
__global__ void init_kernel(float* __restrict__ out) {
    int i = blockIdx.x * blockDim.x + threadIdx.x;
    if (i < NE) g_count[i] = 0;
    int n4 = NT * DOUT / 4;
    if (i < n4) ((float4*)out)[i] = make_float4(0.f, 0.f, 0.f, 0.f);
}

// ---------------- router: 1 warp per token ----------------
__global__ void __launch_bounds__(256) router_kernel(
    const float* __restrict__ x, const float* __restrict__ Wr,
    const float* __restrict__ br)
{
    int warp = threadIdx.x >> 5;
    int lane = threadIdx.x & 31;
    int t = blockIdx.x * 8 + warp;
    if (t >= NT) return;

    const float* xr = x + (size_t)t * DIN;
    float acc[NE];
#pragma unroll
    for (int e = 0; e < NE; e++) acc[e] = 0.f;
    for (int d = lane; d < DIN; d += 32) {
        float xv = xr[d];
        const float* w = Wr + (size_t)d * NE;
#pragma unroll
        for (int e = 0; e < NE; e++) acc[e] += xv * w[e];
    }
#pragma unroll
    for (int e = 0; e < NE; e++) {
#pragma unroll
        for (int off = 16; off; off >>= 1)
            acc[e] += __shfl_xor_sync(0xffffffffu, acc[e], off);
    }
    if (lane == 0) {
        float logit[NE], p[NE];
        float mx = -1e30f;
#pragma unroll
        for (int e = 0; e < NE; e++) { logit[e] = acc[e] + br[e]; mx = fmaxf(mx, logit[e]); }
        float s = 0.f;
#pragma unroll
        for (int e = 0; e < NE; e++) { p[e] = expf(logit[e] - mx); s += p[e]; }
        float inv = 1.f / s;
#pragma unroll
        for (int e = 0; e < NE; e++) p[e] *= inv;
        int i0 = 0;
#pragma unroll
        for (int e = 1; e < NE; e++) if (p[e] > p[i0]) i0 = e;
        int i1 = (i0 == 0) ? 1 : 0;
#pragma unroll
        for (int e = 0; e < NE; e++) { if (e == i0) continue; if (p[e] > p[i1]) i1 = e; }
        int idx[2] = { i0, i1 };
#pragma unroll
        for (int k = 0; k < 2; k++) {
            int e = idx[k];
            int pos = atomicAdd(&g_count[e], 1);
            g_hrow[e][pos] = t * 2 + k;
            g_cw[e][pos]   = p[e];
        }
    }
}

// ============================================================================
// tf32 MMA tile core (R6). BM=128, BN=128, BK=32, 256 thr, 8 warps (2x4),
// warp tile 64x32. A pre-rounded (raw bits); B cvt at fragment load.
// 2-stage cp.async pipeline, 2 syncs per K-tile (ptxas-friendly: 95 regs).
// ============================================================================

template<int N_DIM>
__device__ __forceinline__ void load_tile(
    float* As, float* Bs, const float* __restrict__ Asrc_base,
    const int* s_row, const float* __restrict__ Bsrc,
    int k0, int tid, int a_src_ld)
{
    // A: 128 rows x 32 floats = 1024 float4; 4 per thread (gathered rows)
#pragma unroll
    for (int i = 0; i < 4; i++) {
        int c   = tid + i * 256;
        int row = c >> 3;
        int c4  = (c & 7) * 4;
        const float* src = Asrc_base + (size_t)s_row[row] * a_src_ld + k0 + c4;
        uint32_t dst = (uint32_t)__cvta_generic_to_shared(As + row * A_STRIDE + c4);
        CP_ASYNC16(dst, src);
    }
    // B: 32 rows x 128 floats = 1024 float4; 4 per thread
#pragma unroll
    for (int i = 0; i < 4; i++) {
        int c   = tid + i * 256;
        int row = c >> 5;
        int c4  = (c & 31) * 4;
        const float* src = Bsrc + (size_t)row * N_DIM + c4;
        uint32_t dst = (uint32_t)__cvta_generic_to_shared(Bs + row * B_STRIDE + c4);
        CP_ASYNC16(dst, src);
    }
    CP_COMMIT();
}

__device__ __forceinline__ void compute_tile(
    const float* Asf, const float* Bs, float acc[4][4][4], int lane, int wm, int wn)
{
    const uint32_t* As = (const uint32_t*)Asf;   // pre-rounded: raw bits
    int g  = lane >> 2;
    int t4 = lane & 3;
#pragma unroll
    for (int kk = 0; kk < 4; kk++) {
        int k = kk * 8;
        uint32_t af[4][4];
        uint32_t bf[4][2];
#pragma unroll
        for (int mi = 0; mi < 4; mi++) {
            int r0 = wm * 64 + mi * 16 + g;
            af[mi][0] = As[(r0    ) * A_STRIDE + k + t4    ];
            af[mi][1] = As[(r0 + 8) * A_STRIDE + k + t4    ];
            af[mi][2] = As[(r0    ) * A_STRIDE + k + t4 + 4];
            af[mi][3] = As[(r0 + 8) * A_STRIDE + k + t4 + 4];
        }
#pragma unroll
        for (int ni = 0; ni < 4; ni++) {
            int col = wn * 32 + ni * 8 + g;
            bf[ni][0] = f2tf32(Bs[(k + t4    ) * B_STRIDE + col]);
            bf[ni][1] = f2tf32(Bs[(k + t4 + 4) * B_STRIDE + col]);
        }
#pragma unroll
        for (int mi = 0; mi < 4; mi++)
#pragma unroll
            for (int ni = 0; ni < 4; ni++)
                mma_tf32(acc[mi][ni], af[mi], bf[ni]);
    }
}

// ---------------- GEMM1: h = rna(relu(xr @ W1 + b1)) ----------------
__global__ void __launch_bounds__(256) gemm1_kernel(
    const float* __restrict__ W1, const float* __restrict__ b1)
{
    extern __shared__ float smem[];
    float* As = smem;
    float* Bs = smem + 2 * A_BUF;

    int e = blockIdx.z;
    int count = g_count[e];
    int r0 = blockIdx.y * 128;
    if (r0 >= count) return;
    int n0 = blockIdx.x * 128;

    __shared__ int s_hrow[128];
    __shared__ int s_tok[128];

    int tid = threadIdx.x;
    if (tid < 128) {
        int r = r0 + tid;
        if (r < count) { int hr = g_hrow[e][r]; s_hrow[tid] = hr; s_tok[tid] = hr >> 1; }
        else           { s_hrow[tid] = -1;      s_tok[tid] = g_hrow[e][0] >> 1; }
    }
    __syncthreads();

    const float* W1e = W1 + (size_t)e * DIN * DHID;
    int lane = tid & 31, warp = tid >> 5;
    int wm = warp >> 2, wn = warp & 3;

    float acc[4][4][4];
#pragma unroll
    for (int a = 0; a < 4; a++)
#pragma unroll
        for (int b = 0; b < 4; b++)
#pragma unroll
            for (int c = 0; c < 4; c++) acc[a][b][c] = 0.f;

    const int KT = DIN / 32;
    load_tile<DHID>(As, Bs, &g_xr[0][0], s_tok, W1e + n0, 0, tid, DIN);
    for (int kt = 0; kt < KT; kt++) {
        if (kt + 1 < KT)
            load_tile<DHID>(As + ((kt + 1) & 1) * A_BUF, Bs + ((kt + 1) & 1) * B_BUF,
                            &g_xr[0][0], s_tok, W1e + (size_t)(kt + 1) * 32 * DHID + n0,
                            (kt + 1) * 32, tid, DIN);
        if (kt + 1 < KT) { CP_WAIT(1); } else { CP_WAIT(0); }
        __syncthreads();
        compute_tile(As + (kt & 1) * A_BUF, Bs + (kt & 1) * B_BUF, acc, lane, wm, wn);
        __syncthreads();
    }

    const float* b1e = b1 + (size_t)e * DHID + n0;
    int g = lane >> 2, t4 = lane & 3;
#pragma unroll
    for (int mi = 0; mi < 4; mi++) {
#pragma unroll
        for (int half = 0; half < 2; half++) {
            int m  = wm * 64 + mi * 16 + g + half * 8;
            int hr = s_hrow[m];
            if (hr < 0) continue;
#pragma unroll
            for (int ni = 0; ni < 4; ni++) {
                int col = wn * 32 + ni * 8 + t4 * 2;
                float c0 = acc[mi][ni][half * 2 + 0] + b1e[col];
                float c1 = acc[mi][ni][half * 2 + 1] + b1e[col + 1];
                float2 v = make_float2(rna_f(fmaxf(c0, 0.f)), rna_f(fmaxf(c1, 0.f)));
                *(float2*)(&g_h[hr][n0 + col]) = v;
            }
        }
    }
}

// ---------------- GEMM2 (split-K 2): out[tok] += cw * (h @ W2 [+ b2]) ----------------
__global__ void __launch_bounds__(256) gemm2_kernel(
    const float* __restrict__ W2, const float* __restrict__ b2,
    float* __restrict__ out)
{
    extern __shared__ float smem[];
    float* As = smem;
    float* Bs = smem + 2 * A_BUF;

    int e = blockIdx.z;
    int count = g_count[e];
    int r0 = blockIdx.y * 128;
    if (r0 >= count) return;
    int nb = blockIdx.x & 7;           // n-tile index (DOUT/128 = 8)
    int sk = blockIdx.x >> 3;          // split-K index 0/1
    int n0 = nb * 128;
    int kbase = sk * (DHID / 2);

    __shared__ int   s_hrow[128];
    __shared__ float s_cw[128];

    int tid = threadIdx.x;
    if (tid < 128) {
        int r = r0 + tid;
        if (r < count) { s_hrow[tid] = g_hrow[e][r]; s_cw[tid] = g_cw[e][r]; }
        else           { s_hrow[tid] = g_hrow[e][0]; s_cw[tid] = -1.f; }
    }
    __syncthreads();

    const float* W2e = W2 + (size_t)e * DHID * DOUT + (size_t)kbase * DOUT;
    const float* Ab  = &g_h[0][0] + kbase;
    int lane = tid & 31, warp = tid >> 5;
    int wm = warp >> 2, wn = warp & 3;

    float acc[4][4][4];
#pragma unroll
    for (int a = 0; a < 4; a++)
#pragma unroll
        for (int b = 0; b < 4; b++)
#pragma unroll
            for (int c = 0; c < 4; c++) acc[a][b][c] = 0.f;

    const int KT = (DHID / 2) / 32;
    load_tile<DOUT>(As, Bs, Ab, s_hrow, W2e + n0, 0, tid, DHID);
    for (int kt = 0; kt < KT; kt++) {
        if (kt + 1 < KT)
            load_tile<DOUT>(As + ((kt + 1) & 1) * A_BUF, Bs + ((kt + 1) & 1) * B_BUF,
                            Ab, s_hrow, W2e + (size_t)(kt + 1) * 32 * DOUT + n0,
                            (kt + 1) * 32, tid, DHID);
        if (kt + 1 < KT) { CP_WAIT(1); } else { CP_WAIT(0); }
        __syncthreads();
        compute_tile(As + (kt & 1) * A_BUF, Bs + (kt & 1) * B_BUF, acc, lane, wm, wn);
        __syncthreads();
    }

    const float* b2e = b2 + (size_t)e * DOUT + n0;
    float bscale = (sk == 0) ? 1.f : 0.f;
    int g = lane >> 2, t4 = lane & 3;
#pragma unroll
    for (int mi = 0; mi < 4; mi++) {
#pragma unroll
        for (int half = 0; half < 2; half++) {
            int m  = wm * 64 + mi * 16 + g + half * 8;
            float w = s_cw[m];
            if (w < 0.f) continue;
            int tok = s_hrow[m] >> 1;
#pragma unroll
            for (int ni = 0; ni < 4; ni++) {
                int col = wn * 32 + ni * 8 + t4 * 2;
                float c0 = w * (acc[mi][ni][half * 2 + 0] + bscale * b2e[col]);
                float c1 = w * (acc[mi][ni][half * 2 + 1] + bscale * b2e[col + 1]);
                float* o = out + (size_t)tok * DOUT + n0 + col;
                atomicAdd(o + 0, c0);
                atomicAdd(o + 1, c1);
            }
        }
    }
}

// ---------------- launch ----------------
extern "C" void kernel_launch(void* const* d_in, const int* in_sizes, int n_in,
                              void* d_out, int out_size) {
    const float* x  = (const float*)d_in[0];
    const float* Wr = (const float*)d_in[1];
    const float* br = (const float*)d_in[2];
    const float* W1 = (const float*)d_in[3];
    const float* b1 = (const float*)d_in[4];
    const float* W2 = (const float*)d_in[5];
    const float* b2 = (const float*)d_in[6];
    float* out = (float*)d_out;

    const int smem_bytes = SMEM_FLOATS * 4;   // 70656
    cudaFuncSetAttribute(gemm1_kernel, cudaFuncAttributeMaxDynamicSharedMemorySize, smem_bytes);
    cudaFuncSetAttribute(gemm2_kernel, cudaFuncAttributeMaxDynamicSharedMemorySize, smem_bytes);

    float* xr;  cudaGetSymbolAddress((void**)&xr, g_xr);

    round_x_kernel<<<NT * DIN / 1024, 256>>>(x, xr);
    init_kernel<<<2048, 256>>>(out);
    router_kernel<<<NT / 8, 256>>>(x, Wr, br);
    gemm1_kernel<<<dim3(DHID / 128, NT / 128, NE), 256, smem_bytes>>>(W1, b1);
    gemm2_kernel<<<dim3((DOUT / 128) * 2, NT / 128, NE), 256, smem_bytes>>>(W2, b2, out);
}

// round 10
// speedup vs baseline: 1.4076x; 1.0254x over previous
#include <cuda_runtime.h>
#include <cstdint>

#define NT   2048
#define DIN  1024
#define DHID 4096
#define DOUT 1024
#define NE   8

// ---------------- device scratch ----------------
__device__ int   g_count[NE];
__device__ int   g_hrow[NE][NT];     // hrow = token*2 + k
__device__ float g_cw[NE][NT];       // combine weight
__device__ float g_h[NT * 2][DHID];  // hidden acts (tf32-rounded at write)
__device__ float g_xr[NT][DIN];      // x (tf32-rounded)

// ---------------- helpers ----------------
__device__ __forceinline__ float rna_f(float f) {
    uint32_t u;
    asm volatile("cvt.rna.tf32.f32 %0, %1;" : "=r"(u) : "f"(f));
    return __uint_as_float(u);
}
__device__ __forceinline__ uint32_t f2tf32(float f) {
    uint32_t u;
    asm volatile("cvt.rna.tf32.f32 %0, %1;" : "=r"(u) : "f"(f));
    return u;
}
__device__ __forceinline__ void mma_tf32(float* c, const uint32_t* a, const uint32_t* b) {
    asm volatile(
        "mma.sync.aligned.m16n8k8.row.col.f32.tf32.tf32.f32 "
        "{%0,%1,%2,%3}, {%4,%5,%6,%7}, {%8,%9}, {%0,%1,%2,%3};"
        : "+f"(c[0]), "+f"(c[1]), "+f"(c[2]), "+f"(c[3])
        : "r"(a[0]), "r"(a[1]), "r"(a[2]), "r"(a[3]), "r"(b[0]), "r"(b[1]));
}
__device__ __forceinline__ void ldsm_x4(uint32_t* r, uint32_t saddr) {
    asm volatile("ldmatrix.sync.aligned.m8n8.x4.shared.b16 {%0,%1,%2,%3}, [%4];"
        : "=r"(r[0]), "=r"(r[1]), "=r"(r[2]), "=r"(r[3]) : "r"(saddr));
}
#define CP_ASYNC16(dst, src) \
    asm volatile("cp.async.cg.shared.global [%0], [%1], 16;\n" :: "r"(dst), "l"(src))
#define CP_COMMIT() asm volatile("cp.async.commit_group;\n" ::)
#define CP_WAIT(n)  asm volatile("cp.async.wait_group %0;\n" :: "n"(n))

// smem layout (identical to R2/R6)
#define A_STRIDE 36     // 32 + 4 pad (floats)
#define B_STRIDE 136    // 128 + 8 pad (floats)
#define A_BUF (128 * A_STRIDE)
#define B_BUF (32 * B_STRIDE)
#define SMEM_FLOATS (2 * A_BUF + 2 * B_BUF)   // 17664 floats = 70656 B

// ---------------- prepass: round x (8 MB, ~4us) ----------------
__global__ void round_x_kernel(const float* __restrict__ src, float* __restrict__ dst) {
    int i = blockIdx.x * blockDim.x + threadIdx.x;
    float4 v = ((const float4*)src)[i];
    v.x = rna_f(v.x); v.y = rna_f(v.y); v.z = rna_f(v.z); v.w = rna_f(v.w);
    ((float4*)dst)[i] = v;
}

// ---------------- init ----------------
__global__ void init_kernel(float* __restrict__ out) {
    int i = blockIdx.x * blockDim.x + threadIdx.x;
    if (i < NE) g_count[i] = 0;
    int n4 = NT * DOUT / 4;
    if (i < n4) ((float4*)out)[i] = make_float4(0.f, 0.f, 0.f, 0.f);
}

// ---------------- router: 1 warp per token ----------------
__global__ void __launch_bounds__(256) router_kernel(
    const float* __restrict__ x, const float* __restrict__ Wr,
    const float* __restrict__ br)
{
    int warp = threadIdx.x >> 5;
    int lane = threadIdx.x & 31;
    int t = blockIdx.x * 8 + warp;
    if (t >= NT) return;

    const float* xr = x + (size_t)t * DIN;
    float acc[NE];
#pragma unroll
    for (int e = 0; e < NE; e++) acc[e] = 0.f;
    for (int d = lane; d < DIN; d += 32) {
        float xv = xr[d];
        const float* w = Wr + (size_t)d * NE;
#pragma unroll
        for (int e = 0; e < NE; e++) acc[e] += xv * w[e];
    }
#pragma unroll
    for (int e = 0; e < NE; e++) {
#pragma unroll
        for (int off = 16; off; off >>= 1)
            acc[e] += __shfl_xor_sync(0xffffffffu, acc[e], off);
    }
    if (lane == 0) {
        float logit[NE], p[NE];
        float mx = -1e30f;
#pragma unroll
        for (int e = 0; e < NE; e++) { logit[e] = acc[e] + br[e]; mx = fmaxf(mx, logit[e]); }
        float s = 0.f;
#pragma unroll
        for (int e = 0; e < NE; e++) { p[e] = expf(logit[e] - mx); s += p[e]; }
        float inv = 1.f / s;
#pragma unroll
        for (int e = 0; e < NE; e++) p[e] *= inv;
        int i0 = 0;
#pragma unroll
        for (int e = 1; e < NE; e++) if (p[e] > p[i0]) i0 = e;
        int i1 = (i0 == 0) ? 1 : 0;
#pragma unroll
        for (int e = 0; e < NE; e++) { if (e == i0) continue; if (p[e] > p[i1]) i1 = e; }
        int idx[2] = { i0, i1 };
#pragma unroll
        for (int k = 0; k < 2; k++) {
            int e = idx[k];
            int pos = atomicAdd(&g_count[e], 1);
            g_hrow[e][pos] = t * 2 + k;
            g_cw[e][pos]   = p[e];
        }
    }
}

// ============================================================================
// tf32 MMA tile core (R6 skeleton + ldmatrix A). BM=128, BN=128, BK=32,
// 256 thr, 8 warps (2x4), warp tile 64x32. A pre-rounded + ldmatrix.x4;
// B cvt at fragment load. 2-stage cp.async pipeline, 2 syncs per K-tile.
// ============================================================================

template<int N_DIM>
__device__ __forceinline__ void load_tile(
    float* As, float* Bs, const float* __restrict__ Asrc_base,
    const int* s_row, const float* __restrict__ Bsrc,
    int k0, int tid, int a_src_ld)
{
    // A: 128 rows x 32 floats = 1024 float4; 4 per thread (gathered rows)
#pragma unroll
    for (int i = 0; i < 4; i++) {
        int c   = tid + i * 256;
        int row = c >> 3;
        int c4  = (c & 7) * 4;
        const float* src = Asrc_base + (size_t)s_row[row] * a_src_ld + k0 + c4;
        uint32_t dst = (uint32_t)__cvta_generic_to_shared(As + row * A_STRIDE + c4);
        CP_ASYNC16(dst, src);
    }
    // B: 32 rows x 128 floats = 1024 float4; 4 per thread
#pragma unroll
    for (int i = 0; i < 4; i++) {
        int c   = tid + i * 256;
        int row = c >> 5;
        int c4  = (c & 31) * 4;
        const float* src = Bsrc + (size_t)row * N_DIM + c4;
        uint32_t dst = (uint32_t)__cvta_generic_to_shared(Bs + row * B_STRIDE + c4);
        CP_ASYNC16(dst, src);
    }
    CP_COMMIT();
}

// A fragments via ldmatrix.x4 (mapping verified correct in R7 run)
__device__ __forceinline__ void compute_tile(
    uint32_t As_s, const float* Bs, float acc[4][4][4], int lane, int wm, int wn)
{
    int g  = lane >> 2;
    int t4 = lane & 3;
    int arow  = (lane & 7) + ((lane >> 3) & 1) * 8;  // row within 16-row frag
    int acol4 = (lane >> 4) * 4;                     // 0 or 4 (k-offset)
    uint32_t a_thread = As_s + (uint32_t)(((wm * 64 + arow) * A_STRIDE + acol4) * 4);

#pragma unroll
    for (int kk = 0; kk < 4; kk++) {
        int k = kk * 8;
        uint32_t af[4][4];
        uint32_t bf[4][2];
#pragma unroll
        for (int mi = 0; mi < 4; mi++)
            ldsm_x4(af[mi], a_thread + (uint32_t)(mi * 16 * A_STRIDE * 4 + k * 4));
#pragma unroll
        for (int ni = 0; ni < 4; ni++) {
            int col = wn * 32 + ni * 8 + g;
            bf[ni][0] = f2tf32(Bs[(k + t4    ) * B_STRIDE + col]);
            bf[ni][1] = f2tf32(Bs[(k + t4 + 4) * B_STRIDE + col]);
        }
#pragma unroll
        for (int mi = 0; mi < 4; mi++)
#pragma unroll
            for (int ni = 0; ni < 4; ni++)
                mma_tf32(acc[mi][ni], af[mi], bf[ni]);
    }
}

// ---------------- GEMM1: h = rna(relu(xr @ W1 + b1)) ----------------
__global__ void __launch_bounds__(256) gemm1_kernel(
    const float* __restrict__ W1, const float* __restrict__ b1)
{
    extern __shared__ float smem[];
    float* As = smem;
    float* Bs = smem + 2 * A_BUF;

    int e = blockIdx.z;
    int count = g_count[e];
    int r0 = blockIdx.y * 128;
    if (r0 >= count) return;
    int n0 = blockIdx.x * 128;

    __shared__ int s_hrow[128];
    __shared__ int s_tok[128];

    int tid = threadIdx.x;
    if (tid < 128) {
        int r = r0 + tid;
        if (r < count) { int hr = g_hrow[e][r]; s_hrow[tid] = hr; s_tok[tid] = hr >> 1; }
        else           { s_hrow[tid] = -1;      s_tok[tid] = g_hrow[e][0] >> 1; }
    }
    __syncthreads();

    const float* W1e = W1 + (size_t)e * DIN * DHID;
    int lane = tid & 31, warp = tid >> 5;
    int wm = warp >> 2, wn = warp & 3;

    float acc[4][4][4];
#pragma unroll
    for (int a = 0; a < 4; a++)
#pragma unroll
        for (int b = 0; b < 4; b++)
#pragma unroll
            for (int c = 0; c < 4; c++) acc[a][b][c] = 0.f;

    const int KT = DIN / 32;
    load_tile<DHID>(As, Bs, &g_xr[0][0], s_tok, W1e + n0, 0, tid, DIN);
    for (int kt = 0; kt < KT; kt++) {
        if (kt + 1 < KT)
            load_tile<DHID>(As + ((kt + 1) & 1) * A_BUF, Bs + ((kt + 1) & 1) * B_BUF,
                            &g_xr[0][0], s_tok, W1e + (size_t)(kt + 1) * 32 * DHID + n0,
                            (kt + 1) * 32, tid, DIN);
        if (kt + 1 < KT) { CP_WAIT(1); } else { CP_WAIT(0); }
        __syncthreads();
        compute_tile((uint32_t)__cvta_generic_to_shared(As + (kt & 1) * A_BUF),
                     Bs + (kt & 1) * B_BUF, acc, lane, wm, wn);
        __syncthreads();
    }

    const float* b1e = b1 + (size_t)e * DHID + n0;
    int g = lane >> 2, t4 = lane & 3;
#pragma unroll
    for (int mi = 0; mi < 4; mi++) {
#pragma unroll
        for (int half = 0; half < 2; half++) {
            int m  = wm * 64 + mi * 16 + g + half * 8;
            int hr = s_hrow[m];
            if (hr < 0) continue;
#pragma unroll
            for (int ni = 0; ni < 4; ni++) {
                int col = wn * 32 + ni * 8 + t4 * 2;
                float c0 = acc[mi][ni][half * 2 + 0] + b1e[col];
                float c1 = acc[mi][ni][half * 2 + 1] + b1e[col + 1];
                float2 v = make_float2(rna_f(fmaxf(c0, 0.f)), rna_f(fmaxf(c1, 0.f)));
                *(float2*)(&g_h[hr][n0 + col]) = v;
            }
        }
    }
}

// ---------------- GEMM2: out[tok] += cw * (h @ W2 + b2) ----------------
__global__ void __launch_bounds__(256) gemm2_kernel(
    const float* __restrict__ W2, const float* __restrict__ b2,
    float* __restrict__ out)
{
    extern __shared__ float smem[];
    float* As = smem;
    float* Bs = smem + 2 * A_BUF;

    int e = blockIdx.z;
    int count = g_count[e];
    int r0 = blockIdx.y * 128;
    if (r0 >= count) return;
    int n0 = blockIdx.x * 128;

    __shared__ int   s_hrow[128];
    __shared__ float s_cw[128];

    int tid = threadIdx.x;
    if (tid < 128) {
        int r = r0 + tid;
        if (r < count) { s_hrow[tid] = g_hrow[e][r]; s_cw[tid] = g_cw[e][r]; }
        else           { s_hrow[tid] = g_hrow[e][0]; s_cw[tid] = -1.f; }
    }
    __syncthreads();

    const float* W2e = W2 + (size_t)e * DHID * DOUT;
    int lane = tid & 31, warp = tid >> 5;
    int wm = warp >> 2, wn = warp & 3;

    float acc[4][4][4];
#pragma unroll
    for (int a = 0; a < 4; a++)
#pragma unroll
        for (int b = 0; b < 4; b++)
#pragma unroll
            for (int c = 0; c < 4; c++) acc[a][b][c] = 0.f;

    const int KT = DHID / 32;
    load_tile<DOUT>(As, Bs, &g_h[0][0], s_hrow, W2e + n0, 0, tid, DHID);
    for (int kt = 0; kt < KT; kt++) {
        if (kt + 1 < KT)
            load_tile<DOUT>(As + ((kt + 1) & 1) * A_BUF, Bs + ((kt + 1) & 1) * B_BUF,
                            &g_h[0][0], s_hrow, W2e + (size_t)(kt + 1) * 32 * DOUT + n0,
                            (kt + 1) * 32, tid, DHID);
        if (kt + 1 < KT) { CP_WAIT(1); } else { CP_WAIT(0); }
        __syncthreads();
        compute_tile((uint32_t)__cvta_generic_to_shared(As + (kt & 1) * A_BUF),
                     Bs + (kt & 1) * B_BUF, acc, lane, wm, wn);
        __syncthreads();
    }

    const float* b2e = b2 + (size_t)e * DOUT + n0;
    int g = lane >> 2, t4 = lane & 3;
#pragma unroll
    for (int mi = 0; mi < 4; mi++) {
#pragma unroll
        for (int half = 0; half < 2; half++) {
            int m  = wm * 64 + mi * 16 + g + half * 8;
            float w = s_cw[m];
            if (w < 0.f) continue;
            int tok = s_hrow[m] >> 1;
#pragma unroll
            for (int ni = 0; ni < 4; ni++) {
                int col = wn * 32 + ni * 8 + t4 * 2;
                float c0 = w * (acc[mi][ni][half * 2 + 0] + b2e[col]);
                float c1 = w * (acc[mi][ni][half * 2 + 1] + b2e[col + 1]);
                float* o = out + (size_t)tok * DOUT + n0 + col;
                atomicAdd(o + 0, c0);
                atomicAdd(o + 1, c1);
            }
        }
    }
}

// ---------------- launch ----------------
extern "C" void kernel_launch(void* const* d_in, const int* in_sizes, int n_in,
                              void* d_out, int out_size) {
    const float* x  = (const float*)d_in[0];
    const float* Wr = (const float*)d_in[1];
    const float* br = (const float*)d_in[2];
    const float* W1 = (const float*)d_in[3];
    const float* b1 = (const float*)d_in[4];
    const float* W2 = (const float*)d_in[5];
    const float* b2 = (const float*)d_in[6];
    float* out = (float*)d_out;

    const int smem_bytes = SMEM_FLOATS * 4;   // 70656
    cudaFuncSetAttribute(gemm1_kernel, cudaFuncAttributeMaxDynamicSharedMemorySize, smem_bytes);
    cudaFuncSetAttribute(gemm2_kernel, cudaFuncAttributeMaxDynamicSharedMemorySize, smem_bytes);

    float* xr;  cudaGetSymbolAddress((void**)&xr, g_xr);

    round_x_kernel<<<NT * DIN / 1024, 256>>>(x, xr);
    init_kernel<<<2048, 256>>>(out);
    router_kernel<<<NT / 8, 256>>>(x, Wr, br);
    gemm1_kernel<<<dim3(DHID / 128, NT / 128, NE), 256, smem_bytes>>>(W1, b1);
    gemm2_kernel<<<dim3(DOUT / 128, NT / 128, NE), 256, smem_bytes>>>(W2, b2, out);
}

// round 11
// speedup vs baseline: 1.4108x; 1.0022x over previous
#include <cuda_runtime.h>
#include <cstdint>

#define NT   2048
#define DIN  1024
#define DHID 4096
#define DOUT 1024
#define NE   8

// ---------------- device scratch ----------------
__device__ int   g_count[NE];
__device__ int   g_hrow[NE][NT];     // hrow = token*2 + k
__device__ float g_cw[NE][NT];       // combine weight
__device__ float g_h[NT * 2][DHID];  // hidden acts (tf32-rounded at write)
__device__ float g_xr[NT][DIN];      // x (tf32-rounded)

// ---------------- helpers ----------------
__device__ __forceinline__ float rna_f(float f) {
    uint32_t u;
    asm volatile("cvt.rna.tf32.f32 %0, %1;" : "=r"(u) : "f"(f));
    return __uint_as_float(u);
}
__device__ __forceinline__ uint32_t f2tf32(float f) {
    uint32_t u;
    asm volatile("cvt.rna.tf32.f32 %0, %1;" : "=r"(u) : "f"(f));
    return u;
}
__device__ __forceinline__ void mma_tf32(float* c, const uint32_t* a, const uint32_t* b) {
    asm volatile(
        "mma.sync.aligned.m16n8k8.row.col.f32.tf32.tf32.f32 "
        "{%0,%1,%2,%3}, {%4,%5,%6,%7}, {%8,%9}, {%0,%1,%2,%3};"
        : "+f"(c[0]), "+f"(c[1]), "+f"(c[2]), "+f"(c[3])
        : "r"(a[0]), "r"(a[1]), "r"(a[2]), "r"(a[3]), "r"(b[0]), "r"(b[1]));
}
__device__ __forceinline__ void ldsm_x4(uint32_t* r, uint32_t saddr) {
    asm volatile("ldmatrix.sync.aligned.m8n8.x4.shared.b16 {%0,%1,%2,%3}, [%4];"
        : "=r"(r[0]), "=r"(r[1]), "=r"(r[2]), "=r"(r[3]) : "r"(saddr));
}
#define CP_ASYNC16(dst, src) \
    asm volatile("cp.async.cg.shared.global [%0], [%1], 16;\n" :: "r"(dst), "l"(src))
#define CP_COMMIT() asm volatile("cp.async.commit_group;\n" ::)
#define CP_WAIT(n)  asm volatile("cp.async.wait_group %0;\n" :: "n"(n))

// smem layout (identical to R2/R6)
#define A_STRIDE 36     // 32 + 4 pad (floats)
#define B_STRIDE 136    // 128 + 8 pad (floats)
#define A_BUF (128 * A_STRIDE)
#define B_BUF (32 * B_STRIDE)
#define SMEM_FLOATS (2 * A_BUF + 2 * B_BUF)   // 17664 floats = 70656 B

// ---------------- prepass: round x (8 MB, ~4us) ----------------
__global__ void round_x_kernel(const float* __restrict__ src, float* __restrict__ dst) {
    int i = blockIdx.x * blockDim.x + threadIdx.x;
    float4 v = ((const float4*)src)[i];
    v.x = rna_f(v.x); v.y = rna_f(v.y); v.z = rna_f(v.z); v.w = rna_f(v.w);
    ((float4*)dst)[i] = v;
}

// ---------------- init ----------------
__global__ void init_kernel(float* __restrict__ out) {
    int i = blockIdx.x * blockDim.x + threadIdx.x;
    if (i < NE) g_count[i] = 0;
    int n4 = NT * DOUT / 4;
    if (i < n4) ((float4*)out)[i] = make_float4(0.f, 0.f, 0.f, 0.f);
}

// ---------------- router: 1 warp per token ----------------
__global__ void __launch_bounds__(256) router_kernel(
    const float* __restrict__ x, const float* __restrict__ Wr,
    const float* __restrict__ br)
{
    int warp = threadIdx.x >> 5;
    int lane = threadIdx.x & 31;
    int t = blockIdx.x * 8 + warp;
    if (t >= NT) return;

    const float* xr = x + (size_t)t * DIN;
    float acc[NE];
#pragma unroll
    for (int e = 0; e < NE; e++) acc[e] = 0.f;
    for (int d = lane; d < DIN; d += 32) {
        float xv = xr[d];
        const float* w = Wr + (size_t)d * NE;
#pragma unroll
        for (int e = 0; e < NE; e++) acc[e] += xv * w[e];
    }
#pragma unroll
    for (int e = 0; e < NE; e++) {
#pragma unroll
        for (int off = 16; off; off >>= 1)
            acc[e] += __shfl_xor_sync(0xffffffffu, acc[e], off);
    }
    if (lane == 0) {
        float logit[NE], p[NE];
        float mx = -1e30f;
#pragma unroll
        for (int e = 0; e < NE; e++) { logit[e] = acc[e] + br[e]; mx = fmaxf(mx, logit[e]); }
        float s = 0.f;
#pragma unroll
        for (int e = 0; e < NE; e++) { p[e] = expf(logit[e] - mx); s += p[e]; }
        float inv = 1.f / s;
#pragma unroll
        for (int e = 0; e < NE; e++) p[e] *= inv;
        int i0 = 0;
#pragma unroll
        for (int e = 1; e < NE; e++) if (p[e] > p[i0]) i0 = e;
        int i1 = (i0 == 0) ? 1 : 0;
#pragma unroll
        for (int e = 0; e < NE; e++) { if (e == i0) continue; if (p[e] > p[i1]) i1 = e; }
        int idx[2] = { i0, i1 };
#pragma unroll
        for (int k = 0; k < 2; k++) {
            int e = idx[k];
            int pos = atomicAdd(&g_count[e], 1);
            g_hrow[e][pos] = t * 2 + k;
            g_cw[e][pos]   = p[e];
        }
    }
}

// ============================================================================
// tf32 MMA tile core (R6 skeleton + ldmatrix A). BM=128, BN=128, BK=32,
// 256 thr, 8 warps (2x4), warp tile 64x32. A pre-rounded + ldmatrix.x4;
// B cvt at fragment load. 2-stage cp.async pipeline, 2 syncs per K-tile.
// ============================================================================

template<int N_DIM>
__device__ __forceinline__ void load_tile(
    float* As, float* Bs, const float* __restrict__ Asrc_base,
    const int* s_row, const float* __restrict__ Bsrc,
    int k0, int tid, int a_src_ld)
{
    // A: 128 rows x 32 floats = 1024 float4; 4 per thread (gathered rows)
#pragma unroll
    for (int i = 0; i < 4; i++) {
        int c   = tid + i * 256;
        int row = c >> 3;
        int c4  = (c & 7) * 4;
        const float* src = Asrc_base + (size_t)s_row[row] * a_src_ld + k0 + c4;
        uint32_t dst = (uint32_t)__cvta_generic_to_shared(As + row * A_STRIDE + c4);
        CP_ASYNC16(dst, src);
    }
    // B: 32 rows x 128 floats = 1024 float4; 4 per thread
#pragma unroll
    for (int i = 0; i < 4; i++) {
        int c   = tid + i * 256;
        int row = c >> 5;
        int c4  = (c & 31) * 4;
        const float* src = Bsrc + (size_t)row * N_DIM + c4;
        uint32_t dst = (uint32_t)__cvta_generic_to_shared(Bs + row * B_STRIDE + c4);
        CP_ASYNC16(dst, src);
    }
    CP_COMMIT();
}

// A fragments via ldmatrix.x4 (mapping verified correct in R7 run)
__device__ __forceinline__ void compute_tile(
    uint32_t As_s, const float* Bs, float acc[4][4][4], int lane, int wm, int wn)
{
    int g  = lane >> 2;
    int t4 = lane & 3;
    int arow  = (lane & 7) + ((lane >> 3) & 1) * 8;  // row within 16-row frag
    int acol4 = (lane >> 4) * 4;                     // 0 or 4 (k-offset)
    uint32_t a_thread = As_s + (uint32_t)(((wm * 64 + arow) * A_STRIDE + acol4) * 4);

#pragma unroll
    for (int kk = 0; kk < 4; kk++) {
        int k = kk * 8;
        uint32_t af[4][4];
        uint32_t bf[4][2];
#pragma unroll
        for (int mi = 0; mi < 4; mi++)
            ldsm_x4(af[mi], a_thread + (uint32_t)(mi * 16 * A_STRIDE * 4 + k * 4));
#pragma unroll
        for (int ni = 0; ni < 4; ni++) {
            int col = wn * 32 + ni * 8 + g;
            bf[ni][0] = f2tf32(Bs[(k + t4    ) * B_STRIDE + col]);
            bf[ni][1] = f2tf32(Bs[(k + t4 + 4) * B_STRIDE + col]);
        }
#pragma unroll
        for (int mi = 0; mi < 4; mi++)
#pragma unroll
            for (int ni = 0; ni < 4; ni++)
                mma_tf32(acc[mi][ni], af[mi], bf[ni]);
    }
}

// ---------------- GEMM1: h = rna(relu(xr @ W1 + b1)) ----------------
__global__ void __launch_bounds__(256) gemm1_kernel(
    const float* __restrict__ W1, const float* __restrict__ b1)
{
    extern __shared__ float smem[];
    float* As = smem;
    float* Bs = smem + 2 * A_BUF;

    int e = blockIdx.z;
    int count = g_count[e];
    int r0 = blockIdx.y * 128;
    if (r0 >= count) return;
    int n0 = blockIdx.x * 128;

    __shared__ int s_hrow[128];
    __shared__ int s_tok[128];

    int tid = threadIdx.x;
    if (tid < 128) {
        int r = r0 + tid;
        if (r < count) { int hr = g_hrow[e][r]; s_hrow[tid] = hr; s_tok[tid] = hr >> 1; }
        else           { s_hrow[tid] = -1;      s_tok[tid] = g_hrow[e][0] >> 1; }
    }
    __syncthreads();

    const float* W1e = W1 + (size_t)e * DIN * DHID;
    int lane = tid & 31, warp = tid >> 5;
    int wm = warp >> 2, wn = warp & 3;

    float acc[4][4][4];
#pragma unroll
    for (int a = 0; a < 4; a++)
#pragma unroll
        for (int b = 0; b < 4; b++)
#pragma unroll
            for (int c = 0; c < 4; c++) acc[a][b][c] = 0.f;

    const int KT = DIN / 32;
    load_tile<DHID>(As, Bs, &g_xr[0][0], s_tok, W1e + n0, 0, tid, DIN);
    for (int kt = 0; kt < KT; kt++) {
        if (kt + 1 < KT)
            load_tile<DHID>(As + ((kt + 1) & 1) * A_BUF, Bs + ((kt + 1) & 1) * B_BUF,
                            &g_xr[0][0], s_tok, W1e + (size_t)(kt + 1) * 32 * DHID + n0,
                            (kt + 1) * 32, tid, DIN);
        if (kt + 1 < KT) { CP_WAIT(1); } else { CP_WAIT(0); }
        __syncthreads();
        compute_tile((uint32_t)__cvta_generic_to_shared(As + (kt & 1) * A_BUF),
                     Bs + (kt & 1) * B_BUF, acc, lane, wm, wn);
        __syncthreads();
    }

    const float* b1e = b1 + (size_t)e * DHID + n0;
    int g = lane >> 2, t4 = lane & 3;
#pragma unroll
    for (int mi = 0; mi < 4; mi++) {
#pragma unroll
        for (int half = 0; half < 2; half++) {
            int m  = wm * 64 + mi * 16 + g + half * 8;
            int hr = s_hrow[m];
            if (hr < 0) continue;
#pragma unroll
            for (int ni = 0; ni < 4; ni++) {
                int col = wn * 32 + ni * 8 + t4 * 2;
                float c0 = acc[mi][ni][half * 2 + 0] + b1e[col];
                float c1 = acc[mi][ni][half * 2 + 1] + b1e[col + 1];
                float2 v = make_float2(rna_f(fmaxf(c0, 0.f)), rna_f(fmaxf(c1, 0.f)));
                *(float2*)(&g_h[hr][n0 + col]) = v;
            }
        }
    }
}

// ---------------- GEMM2: out[tok] += cw * (h @ W2 + b2) ----------------
__global__ void __launch_bounds__(256) gemm2_kernel(
    const float* __restrict__ W2, const float* __restrict__ b2,
    float* __restrict__ out)
{
    extern __shared__ float smem[];
    float* As = smem;
    float* Bs = smem + 2 * A_BUF;

    int e = blockIdx.z;
    int count = g_count[e];
    int r0 = blockIdx.y * 128;
    if (r0 >= count) return;
    int n0 = blockIdx.x * 128;

    __shared__ int   s_hrow[128];
    __shared__ float s_cw[128];

    int tid = threadIdx.x;
    if (tid < 128) {
        int r = r0 + tid;
        if (r < count) { s_hrow[tid] = g_hrow[e][r]; s_cw[tid] = g_cw[e][r]; }
        else           { s_hrow[tid] = g_hrow[e][0]; s_cw[tid] = -1.f; }
    }
    __syncthreads();

    const float* W2e = W2 + (size_t)e * DHID * DOUT;
    int lane = tid & 31, warp = tid >> 5;
    int wm = warp >> 2, wn = warp & 3;

    float acc[4][4][4];
#pragma unroll
    for (int a = 0; a < 4; a++)
#pragma unroll
        for (int b = 0; b < 4; b++)
#pragma unroll
            for (int c = 0; c < 4; c++) acc[a][b][c] = 0.f;

    const int KT = DHID / 32;
    load_tile<DOUT>(As, Bs, &g_h[0][0], s_hrow, W2e + n0, 0, tid, DHID);
    for (int kt = 0; kt < KT; kt++) {
        if (kt + 1 < KT)
            load_tile<DOUT>(As + ((kt + 1) & 1) * A_BUF, Bs + ((kt + 1) & 1) * B_BUF,
                            &g_h[0][0], s_hrow, W2e + (size_t)(kt + 1) * 32 * DOUT + n0,
                            (kt + 1) * 32, tid, DHID);
        if (kt + 1 < KT) { CP_WAIT(1); } else { CP_WAIT(0); }
        __syncthreads();
        compute_tile((uint32_t)__cvta_generic_to_shared(As + (kt & 1) * A_BUF),
                     Bs + (kt & 1) * B_BUF, acc, lane, wm, wn);
        __syncthreads();
    }

    const float* b2e = b2 + (size_t)e * DOUT + n0;
    int g = lane >> 2, t4 = lane & 3;
#pragma unroll
    for (int mi = 0; mi < 4; mi++) {
#pragma unroll
        for (int half = 0; half < 2; half++) {
            int m  = wm * 64 + mi * 16 + g + half * 8;
            float w = s_cw[m];
            if (w < 0.f) continue;
            int tok = s_hrow[m] >> 1;
#pragma unroll
            for (int ni = 0; ni < 4; ni++) {
                int col = wn * 32 + ni * 8 + t4 * 2;
                float c0 = w * (acc[mi][ni][half * 2 + 0] + b2e[col]);
                float c1 = w * (acc[mi][ni][half * 2 + 1] + b2e[col + 1]);
                float* o = out + (size_t)tok * DOUT + n0 + col;
                atomicAdd(o + 0, c0);
                atomicAdd(o + 1, c1);
            }
        }
    }
}

// ---------------- launch ----------------
extern "C" void kernel_launch(void* const* d_in, const int* in_sizes, int n_in,
                              void* d_out, int out_size) {
    const float* x  = (const float*)d_in[0];
    const float* Wr = (const float*)d_in[1];
    const float* br = (const float*)d_in[2];
    const float* W1 = (const float*)d_in[3];
    const float* b1 = (const float*)d_in[4];
    const float* W2 = (const float*)d_in[5];
    const float* b2 = (const float*)d_in[6];
    float* out = (float*)d_out;

    const int smem_bytes = SMEM_FLOATS * 4;   // 70656
    cudaFuncSetAttribute(gemm1_kernel, cudaFuncAttributeMaxDynamicSharedMemorySize, smem_bytes);
    cudaFuncSetAttribute(gemm2_kernel, cudaFuncAttributeMaxDynamicSharedMemorySize, smem_bytes);

    float* xr;  cudaGetSymbolAddress((void**)&xr, g_xr);

    round_x_kernel<<<NT * DIN / 1024, 256>>>(x, xr);
    init_kernel<<<2048, 256>>>(out);
    router_kernel<<<NT / 8, 256>>>(x, Wr, br);
    gemm1_kernel<<<dim3(DHID / 128, NT / 128, NE), 256, smem_bytes>>>(W1, b1);
    gemm2_kernel<<<dim3(DOUT / 128, NT / 128, NE), 256, smem_bytes>>>(W2, b2, out);
}